// round 3
// baseline (speedup 1.0000x reference)
#include <cuda_runtime.h>
#include <cstdint>

// ---------------------------------------------------------------- constants
#define NXG        128
#define ROWS_PER   16
#define NRANK      8
#define TSTEPS     256
#define NSRC       2
#define NPROBE     4
#define RELAXN     100
#define NTHREADS   512

#define F_H      ((float)(175950000000.0 * 1e-13))        // GAMMA*DT
#define F_H2     (0.5f * F_H)
#define F_H6     ((float)(175950000000.0 * 1e-13 / 6.0))
#define F_MU0    ((float)(4e-07 * 3.14159265358979323846)) // MU0
#define F_A2     ((float)(2.0 * 1.3e-11))                  // 2*A_EX
#define F_CSOT   (0.001f)
#define F_INVDX2 (1.0f / ((float)(5e-09 * 5e-09)))
#define F_ALPHA_R 0.5f
#define F_INV_R   ((float)(1.0 / (1.0 + 0.5 * 0.5)))
#define F_ALPHA_D 0.02f
#define F_INV_D   ((float)(1.0 / (1.0 + 0.02 * 0.02)))

// buffer: [comp][row -1..16][col], 3*18*128 floats each
__device__ __forceinline__ int bidx(int c, int r, int col) {
    return (c * 18 + (r + 1)) * NXG + col;
}

__device__ __forceinline__ void cluster_sync() {
    asm volatile("barrier.cluster.arrive.aligned;" ::: "memory");
    asm volatile("barrier.cluster.wait.aligned;" ::: "memory");
}

// remote SMEM store of a float4 into another CTA of the cluster
__device__ __forceinline__ void dsmem_st4(float* local_ptr, unsigned rank, float4 v) {
    uint32_t a = (uint32_t)__cvta_generic_to_shared(local_ptr);
    uint32_t ra;
    asm volatile("mapa.shared::cluster.u32 %0, %1, %2;" : "=r"(ra) : "r"(a), "r"(rank));
    asm volatile("st.shared::cluster.v4.f32 [%0], {%1,%2,%3,%4};"
                 :: "r"(ra), "f"(v.x), "f"(v.y), "f"(v.z), "f"(v.w) : "memory");
}

// store 4-cell value into dst interior + push ghost copies to neighbors
__device__ __forceinline__ void store_with_ghost(float* dst, int lrow, int col,
                                                 unsigned rank, const float v[3][4]) {
#pragma unroll
    for (int c = 0; c < 3; c++) {
        float4 f = make_float4(v[c][0], v[c][1], v[c][2], v[c][3]);
        *(float4*)(dst + bidx(c, lrow, col)) = f;
        if (lrow == 0) {
            if (rank > 0) dsmem_st4(dst + bidx(c, ROWS_PER, col), rank - 1, f);
            else          *(float4*)(dst + bidx(c, -1, col)) = f;   // edge replicate
        }
        if (lrow == ROWS_PER - 1) {
            if (rank < NRANK - 1) dsmem_st4(dst + bidx(c, -1, col), rank + 1, f);
            else                  *(float4*)(dst + bidx(c, ROWS_PER, col)) = f;
        }
    }
}

// one RK4 stage: read stage field from src, produce k, update accumulators,
// write next stage field (or final m) to dst (+ ghost push).
template <int S>
__device__ __forceinline__ void stage(const float* __restrict__ src, float* __restrict__ dst,
                                      int lrow, int col, unsigned rank,
                                      float (&mx)[4], float (&my)[4], float (&mz)[4],
                                      float (&kax)[4], float (&kay)[4], float (&kaz)[4],
                                      const float (&Bx)[4], const float (&By)[4], const float (&Bz)[4],
                                      const float (&cex)[4], const float (&cdem)[4],
                                      float alpha, float inv) {
    float mst[3][4], lap[3][4];
#pragma unroll
    for (int c = 0; c < 3; c++) {
        const float* base = src + bidx(c, lrow, col);
        float4 ctr = *(const float4*)base;
        float4 up  = *(const float4*)(src + bidx(c, lrow - 1, col));
        float4 dn  = *(const float4*)(src + bidx(c, lrow + 1, col));
        float lf = (col == 0)       ? ctr.x : base[-1];
        float rt = (col == NXG - 4) ? ctr.w : base[4];
        mst[c][0] = ctr.x; mst[c][1] = ctr.y; mst[c][2] = ctr.z; mst[c][3] = ctr.w;
        // match JAX order: down + up + right + left - 4*m
        lap[c][0] = (dn.x + up.x + ctr.y + lf    - 4.0f * ctr.x) * F_INVDX2;
        lap[c][1] = (dn.y + up.y + ctr.z + ctr.x - 4.0f * ctr.y) * F_INVDX2;
        lap[c][2] = (dn.z + up.z + ctr.w + ctr.y - 4.0f * ctr.z) * F_INVDX2;
        lap[c][3] = (dn.w + up.w + rt    + ctr.z - 4.0f * ctr.w) * F_INVDX2;
    }
    float nin[3][4];
#pragma unroll
    for (int j = 0; j < 4; j++) {
        float ax = mst[0][j], ay = mst[1][j], az = mst[2][j];
        float bx = Bx[j] + cex[j] * lap[0][j];
        float by = By[j] + cex[j] * lap[1][j];
        float bz = Bz[j] + cex[j] * lap[2][j] + cdem[j] * az;
        // c1 = m x b
        float c1x = ay * bz - az * by;
        float c1y = az * bx - ax * bz;
        float c1z = ax * by - ay * bx;
        // c2 = m x c1
        float c2x = ay * c1z - az * c1y;
        float c2y = az * c1x - ax * c1z;
        float c2z = ax * c1y - ay * c1x;
        // sot = C * m x (m x yhat) = C*(ax*ay, -(az^2+ax^2), ay*az)
        float sx = F_CSOT * (ay * ax);
        float sy = F_CSOT * (az * (-az) - ax * ax);
        float sz = F_CSOT * (ay * az);
        float kx = -inv * (c1x + alpha * c2x) + sx;
        float ky = -inv * (c1y + alpha * c2y) + sy;
        float kz = -inv * (c1z + alpha * c2z) + sz;

        if (S == 0)      { kax[j] = kx;          kay[j] = ky;          kaz[j] = kz; }
        else if (S < 3)  { kax[j] += 2.0f * kx;  kay[j] += 2.0f * ky;  kaz[j] += 2.0f * kz; }

        if (S < 3) {
            const float cc = (S == 2) ? F_H : F_H2;
            nin[0][j] = mx[j] + cc * kx;
            nin[1][j] = my[j] + cc * ky;
            nin[2][j] = mz[j] + cc * kz;
        } else {
            mx[j] = mx[j] + F_H6 * (kax[j] + kx);
            my[j] = my[j] + F_H6 * (kay[j] + ky);
            mz[j] = mz[j] + F_H6 * (kaz[j] + kz);
            nin[0][j] = mx[j]; nin[1][j] = my[j]; nin[2][j] = mz[j];
        }
    }
    store_with_ghost(dst, lrow, col, rank, nin);
}

__global__ void __cluster_dims__(NRANK, 1, 1) __launch_bounds__(NTHREADS, 1)
mm_solver_kernel(const float* __restrict__ sig, const float* __restrict__ Bext,
                 const float* __restrict__ Msat, const int* __restrict__ srcidx,
                 const int* __restrict__ probeidx, float* __restrict__ out) {
    extern __shared__ float smem[];
    float* bufA = smem;                       // 3*18*128
    float* bufB = smem + 3 * 18 * NXG;        // 3*18*128
    float* sigs = smem + 2 * 3 * 18 * NXG;    // 512

    const unsigned rank = blockIdx.x;
    const int tid  = threadIdx.x;
    const int lrow = tid >> 5;            // 0..15
    const int col  = (tid & 31) * 4;      // 0,4,...,124
    const int grow = (int)rank * ROWS_PER + lrow;

    // signal -> smem (512 elements, 512 threads)
    sigs[tid] = sig[tid];

    // per-cell register state
    float mx[4], my[4], mz[4];
    float kax[4], kay[4], kaz[4];
    float Bx[4], By[4], Bz[4];
    float cex[4], cdem[4];
    float m0z[4], pmsat[4];
    unsigned meta = 0;  // per cell j (byte j): bits0-3 probe mask, bits4-5 srcid+1

    const int s0r = srcidx[0], s0c = srcidx[1];
    const int s1r = srcidx[2], s1c = srcidx[3];

#pragma unroll
    for (int j = 0; j < 4; j++) {
        int gc = grow * NXG + col + j;
        float ms = Msat[gc];
        cex[j]  = F_A2 / ms;
        cdem[j] = -F_MU0 * ms;
        Bx[j] = Bext[gc];
        By[j] = Bext[NXG * NXG + gc];
        Bz[j] = Bext[2 * NXG * NXG + gc];
        mx[j] = 0.0f; my[j] = 1.0f; mz[j] = 0.0f;
        kax[j] = kay[j] = kaz[j] = 0.0f;
        m0z[j] = 0.0f; pmsat[j] = ms;
        unsigned mb = 0;
        if (grow == s0r && (col + j) == s0c) mb = 1u << 4;
        if (grow == s1r && (col + j) == s1c) mb = 2u << 4;
#pragma unroll
        for (int p = 0; p < NPROBE; p++) {
            if (grow == probeidx[2 * p] && (col + j) == probeidx[2 * p + 1]) mb |= 1u << p;
        }
        meta |= mb << (8 * j);
    }

    // init bufA = m (incl. ghosts)
    {
        float v[3][4];
#pragma unroll
        for (int j = 0; j < 4; j++) { v[0][j] = mx[j]; v[1][j] = my[j]; v[2][j] = mz[j]; }
        store_with_ghost(bufA, lrow, col, rank, v);
    }
    cluster_sync();

    // single call site for all 356 RK4 steps (relax 100 + drive 256)
    for (int it = 0; it < RELAXN + TSTEPS; ++it) {
        const bool drive = (it >= RELAXN);
        const int  t     = it - RELAXN;
        const float alpha = drive ? F_ALPHA_D : F_ALPHA_R;
        const float inv   = drive ? F_INV_D   : F_INV_R;

        if (drive) {
            if (t == 0) {  // capture m0 (z at probe cells) after relax
#pragma unroll
                for (int j = 0; j < 4; j++)
                    if ((meta >> (8 * j)) & 0xFu) m0z[j] = mz[j];
            }
            // inject source signal into Bz registers (set semantics)
#pragma unroll
            for (int j = 0; j < 4; j++) {
                unsigned sid = (meta >> (8 * j + 4)) & 3u;
                if (sid) Bz[j] = sigs[t * NSRC + (int)(sid - 1u)];
            }
        }

        stage<0>(bufA, bufB, lrow, col, rank, mx, my, mz, kax, kay, kaz, Bx, By, Bz, cex, cdem, alpha, inv);
        cluster_sync();
        stage<1>(bufB, bufA, lrow, col, rank, mx, my, mz, kax, kay, kaz, Bx, By, Bz, cex, cdem, alpha, inv);
        cluster_sync();
        stage<2>(bufA, bufB, lrow, col, rank, mx, my, mz, kax, kay, kaz, Bx, By, Bz, cex, cdem, alpha, inv);
        cluster_sync();
        stage<3>(bufB, bufA, lrow, col, rank, mx, my, mz, kax, kay, kaz, Bx, By, Bz, cex, cdem, alpha, inv);
        cluster_sync();

        if (drive) {
            // probe readout: (mz - m0z) * Msat, straight from registers
#pragma unroll
            for (int j = 0; j < 4; j++) {
                unsigned pm = (meta >> (8 * j)) & 0xFu;
                if (pm) {
                    float v = (mz[j] - m0z[j]) * pmsat[j];
#pragma unroll
                    for (int p = 0; p < NPROBE; p++)
                        if (pm & (1u << p)) out[t * NPROBE + p] = v;
                }
            }
        }
    }
}

extern "C" void kernel_launch(void* const* d_in, const int* in_sizes, int n_in,
                              void* d_out, int out_size) {
    (void)in_sizes; (void)n_in; (void)out_size;
    const float* sig    = (const float*)d_in[0];
    const float* Bext   = (const float*)d_in[1];
    const float* Msat   = (const float*)d_in[2];
    const int*   srci   = (const int*)d_in[3];
    const int*   probei = (const int*)d_in[4];
    float* out = (float*)d_out;

    const size_t smem_bytes = (size_t)(2 * 3 * 18 * NXG + NTHREADS) * sizeof(float);
    cudaFuncSetAttribute(mm_solver_kernel,
                         cudaFuncAttributeMaxDynamicSharedMemorySize, (int)smem_bytes);
    mm_solver_kernel<<<NRANK, NTHREADS, smem_bytes>>>(sig, Bext, Msat, srci, probei, out);
}

// round 6
// speedup vs baseline: 1.1959x; 1.1959x over previous
#include <cuda_runtime.h>
#include <cstdint>

// ---------------------------------------------------------------- constants
#define NXG        128
#define ROWS_PER   16
#define NRANK      8
#define TSTEPS     256
#define NSRC       2
#define NPROBE     4
#define RELAXN     100
#define NTHREADS   512

#define F_H      ((float)(175950000000.0 * 1e-13))        // GAMMA*DT
#define F_H2     (0.5f * F_H)
#define F_H6     ((float)(175950000000.0 * 1e-13 / 6.0))
#define F_MU0    ((float)(4e-07 * 3.14159265358979323846)) // MU0
#define F_A2     ((float)(2.0 * 1.3e-11))                  // 2*A_EX
#define F_CSOT   (0.001f)
#define F_INVDX2 (1.0f / ((float)(5e-09 * 5e-09)))
#define F_ALPHA_R 0.5f
#define F_INV_R   ((float)(1.0 / (1.0 + 0.5 * 0.5)))
#define F_ALPHA_D 0.02f
#define F_INV_D   ((float)(1.0 / (1.0 + 0.02 * 0.02)))

// ---------------------------------------------------------------- smem map (floats)
#define BUF_FLOATS   (3 * 18 * NXG)          // 6912
#define BUFA_OFF     0
#define BUFB_OFF     BUF_FLOATS              // 6912
#define SIGS_OFF     (2 * BUF_FLOATS)        // 13824
#define MBARU_OFF    (SIGS_OFF + NTHREADS)   // 14336 (byte 57344, 8B aligned)
#define MBARD_OFF    (MBARU_OFF + 2)         // 14338
#define PMS_OFF      (MBARD_OFF + 2)         // 14340
#define PM0_OFF      (PMS_OFF + 4)           // 14344
#define SMEM_FLOATS  (PM0_OFF + 4)           // 14348

// buffer: [comp][row -1..16][col]
__device__ __forceinline__ int bidx(int c, int r, int col) {
    return (c * 18 + (r + 1)) * NXG + col;
}

// ---------------------------------------------------------------- ptx helpers
__device__ __forceinline__ void cluster_sync_full() {
    asm volatile("barrier.cluster.arrive.aligned;" ::: "memory");
    asm volatile("barrier.cluster.wait.aligned;" ::: "memory");
}
__device__ __forceinline__ uint32_t smem_u32(const void* p) {
    return (uint32_t)__cvta_generic_to_shared(p);
}
__device__ __forceinline__ uint32_t mapa_rank(uint32_t laddr, unsigned r) {
    uint32_t ra;
    asm("mapa.shared::cluster.u32 %0, %1, %2;" : "=r"(ra) : "r"(laddr), "r"(r));
    return ra;
}
__device__ __forceinline__ void st_cluster4(uint32_t addr, float4 v) {
    asm volatile("st.shared::cluster.v4.f32 [%0], {%1,%2,%3,%4};"
                 :: "r"(addr), "f"(v.x), "f"(v.y), "f"(v.z), "f"(v.w) : "memory");
}
__device__ __forceinline__ void mbar_init(uint32_t addr, unsigned cnt) {
    asm volatile("mbarrier.init.shared.b64 [%0], %1;" :: "r"(addr), "r"(cnt) : "memory");
}
__device__ __forceinline__ void mbar_arrive_remote(uint32_t raddr) {
    asm volatile("mbarrier.arrive.release.cluster.shared::cluster.b64 _, [%0];"
                 :: "r"(raddr) : "memory");
}
__device__ __forceinline__ void mbar_wait(uint32_t addr, uint32_t parity) {
    asm volatile(
        "{\n\t"
        ".reg .pred P;\n\t"
        "WL_%=:\n\t"
        "mbarrier.try_wait.parity.acquire.cluster.shared::cta.b64 P, [%0], %1, 0x989680;\n\t"
        "@P bra WD_%=;\n\t"
        "bra WL_%=;\n\t"
        "WD_%=:\n\t"
        "}" :: "r"(addr), "r"(parity) : "memory");
}

// ---------------------------------------------------------------- one RK4 stage
// Stage field lives in registers (sf). SMEM holds it only so neighbors can read
// up/dn rows; left/right neighbors come via lane shuffles.
template <int S>
__device__ __forceinline__ void stage(const float* __restrict__ src, float* __restrict__ dst,
                                      uint32_t dstByteOff,
                                      int lrow, int col, int lane,
                                      bool pushUp, bool pushDn, bool edgeUp, bool edgeDn,
                                      uint32_t remUpBase, uint32_t remDnBase,
                                      float (&sf)[3][4],
                                      float (&mx)[4], float (&my)[4], float (&mz)[4],
                                      float (&ka)[3][4],
                                      const float (&Bx)[4], const float (&By)[4], const float (&Bz)[4],
                                      const float (&cex)[4], const float (&cdem)[4],
                                      float alpha, float inv) {
    // vertical neighbors from SMEM (6 x LDS.128, issued back-to-back)
    float u[3][4], d[3][4];
#pragma unroll
    for (int c = 0; c < 3; c++) {
        float4 uv = *(const float4*)(src + bidx(c, lrow - 1, col));
        float4 dv = *(const float4*)(src + bidx(c, lrow + 1, col));
        u[c][0] = uv.x; u[c][1] = uv.y; u[c][2] = uv.z; u[c][3] = uv.w;
        d[c][0] = dv.x; d[c][1] = dv.y; d[c][2] = dv.z; d[c][3] = dv.w;
    }
    // horizontal neighbors via shuffle (edge-replicate at lanes 0/31)
    float lfv[3], rtv[3];
#pragma unroll
    for (int c = 0; c < 3; c++) {
        float l = __shfl_up_sync(0xffffffffu, sf[c][3], 1);
        float r = __shfl_down_sync(0xffffffffu, sf[c][0], 1);
        lfv[c] = (lane == 0)  ? sf[c][0] : l;
        rtv[c] = (lane == 31) ? sf[c][3] : r;
    }

    float nin[3][4];
#pragma unroll
    for (int j = 0; j < 4; j++) {
        float lap[3];
#pragma unroll
        for (int c = 0; c < 3; c++) {
            float lv = (j == 0) ? lfv[c] : sf[c][j - 1];
            float rv = (j == 3) ? rtv[c] : sf[c][j + 1];
            // match JAX order: down + up + right + left - 4*m
            lap[c] = (d[c][j] + u[c][j] + rv + lv - 4.0f * sf[c][j]) * F_INVDX2;
        }
        float ax = sf[0][j], ay = sf[1][j], az = sf[2][j];
        float bx = Bx[j] + cex[j] * lap[0];
        float by = By[j] + cex[j] * lap[1];
        float bz = Bz[j] + cex[j] * lap[2] + cdem[j] * az;
        // c1 = m x b
        float c1x = ay * bz - az * by;
        float c1y = az * bx - ax * bz;
        float c1z = ax * by - ay * bx;
        // c2 = m x c1
        float c2x = ay * c1z - az * c1y;
        float c2y = az * c1x - ax * c1z;
        float c2z = ax * c1y - ay * c1x;
        // sot = C_SOT * m x (m x yhat)
        float sx = F_CSOT * (ay * ax);
        float sy = F_CSOT * (az * (-az) - ax * ax);
        float sz = F_CSOT * (ay * az);
        float kx = -inv * (c1x + alpha * c2x) + sx;
        float ky = -inv * (c1y + alpha * c2y) + sy;
        float kz = -inv * (c1z + alpha * c2z) + sz;

        if (S == 0)      { ka[0][j] = kx;         ka[1][j] = ky;         ka[2][j] = kz; }
        else if (S < 3)  { ka[0][j] += 2.0f * kx; ka[1][j] += 2.0f * ky; ka[2][j] += 2.0f * kz; }

        if (S < 3) {
            const float cc = (S == 2) ? F_H : F_H2;
            nin[0][j] = mx[j] + cc * kx;
            nin[1][j] = my[j] + cc * ky;
            nin[2][j] = mz[j] + cc * kz;
        } else {
            mx[j] = mx[j] + F_H6 * (ka[0][j] + kx);
            my[j] = my[j] + F_H6 * (ka[1][j] + ky);
            mz[j] = mz[j] + F_H6 * (ka[2][j] + kz);
            nin[0][j] = mx[j]; nin[1][j] = my[j]; nin[2][j] = mz[j];
        }
    }

    // store interior row + ghost push / edge replicate; update register stage field
#pragma unroll
    for (int c = 0; c < 3; c++) {
        float4 f = make_float4(nin[c][0], nin[c][1], nin[c][2], nin[c][3]);
        *(float4*)(dst + bidx(c, lrow, col)) = f;
        if (pushUp)      st_cluster4(remUpBase + 4u * (dstByteOff + (uint32_t)bidx(c, ROWS_PER, col)), f);
        else if (edgeUp) *(float4*)(dst + bidx(c, -1, col)) = f;
        if (pushDn)      st_cluster4(remDnBase + 4u * (dstByteOff + (uint32_t)bidx(c, -1, col)), f);
        else if (edgeDn) *(float4*)(dst + bidx(c, ROWS_PER, col)) = f;
        sf[c][0] = nin[c][0]; sf[c][1] = nin[c][1]; sf[c][2] = nin[c][2]; sf[c][3] = nin[c][3];
    }
}

// per-stage sync tail: arrives are remote (to the neighbor that consumes our ghost),
// waits are local and only done by boundary warps.
__device__ __forceinline__ void sync_tail(uint32_t parity,
                                          bool pushUp, bool pushDn,
                                          uint32_t mbarUp, uint32_t mbarDn,
                                          uint32_t remArrUp, uint32_t remArrDn) {
    if (pushUp) mbar_arrive_remote(remArrUp);  // signal rank-1's mbar_dn
    if (pushDn) mbar_arrive_remote(remArrDn);  // signal rank+1's mbar_up
    __syncthreads();
    if (pushUp) mbar_wait(mbarUp, parity);     // wait for rank-1's lrow15 ghosts
    if (pushDn) mbar_wait(mbarDn, parity);     // wait for rank+1's lrow0 ghosts
}

#define STAGE4(SRC, DST, DSTOFF_A, DSTOFF_B, ALPHA, INV)                                          \
    stage<0>(SRC, DST, DSTOFF_B, lrow, col, lane, pushUp, pushDn, edgeUp, edgeDn,                 \
             remUpBase, remDnBase, sf, mx, my, mz, ka, Bx, By, Bz, cex, cdem, ALPHA, INV);        \
    sync_tail(0u, pushUp, pushDn, mbarUp, mbarDn, remArrUp, remArrDn);                            \
    stage<1>(DST, SRC, DSTOFF_A, lrow, col, lane, pushUp, pushDn, edgeUp, edgeDn,                 \
             remUpBase, remDnBase, sf, mx, my, mz, ka, Bx, By, Bz, cex, cdem, ALPHA, INV);        \
    sync_tail(1u, pushUp, pushDn, mbarUp, mbarDn, remArrUp, remArrDn);                            \
    stage<2>(SRC, DST, DSTOFF_B, lrow, col, lane, pushUp, pushDn, edgeUp, edgeDn,                 \
             remUpBase, remDnBase, sf, mx, my, mz, ka, Bx, By, Bz, cex, cdem, ALPHA, INV);        \
    sync_tail(0u, pushUp, pushDn, mbarUp, mbarDn, remArrUp, remArrDn);                            \
    stage<3>(DST, SRC, DSTOFF_A, lrow, col, lane, pushUp, pushDn, edgeUp, edgeDn,                 \
             remUpBase, remDnBase, sf, mx, my, mz, ka, Bx, By, Bz, cex, cdem, ALPHA, INV);        \
    sync_tail(1u, pushUp, pushDn, mbarUp, mbarDn, remArrUp, remArrDn);

__global__ void __cluster_dims__(NRANK, 1, 1) __launch_bounds__(NTHREADS, 1)
mm_solver_kernel(const float* __restrict__ sig, const float* __restrict__ Bext,
                 const float* __restrict__ Msat, const int* __restrict__ srcidx,
                 const int* __restrict__ probeidx, float* __restrict__ out) {
    extern __shared__ float smem[];
    float* bufA = smem + BUFA_OFF;
    float* bufB = smem + BUFB_OFF;
    float* sigs = smem + SIGS_OFF;
    float* pms  = smem + PMS_OFF;
    float* pm0  = smem + PM0_OFF;

    const unsigned rank = blockIdx.x;
    const int tid  = threadIdx.x;
    const int lrow = tid >> 5;            // 0..15 (warp-uniform)
    const int lane = tid & 31;
    const int col  = lane * 4;            // 0,4,...,124
    const int grow = (int)rank * ROWS_PER + lrow;

    const bool pushUp = (lrow == 0)            && (rank > 0);
    const bool edgeUp = (lrow == 0)            && (rank == 0);
    const bool pushDn = (lrow == ROWS_PER - 1) && (rank < NRANK - 1);
    const bool edgeDn = (lrow == ROWS_PER - 1) && (rank == NRANK - 1);

    const uint32_t smemBase = smem_u32(smem);
    const uint32_t mbarUp   = smemBase + 4u * MBARU_OFF;
    const uint32_t mbarDn   = smemBase + 4u * MBARD_OFF;
    uint32_t remUpBase = 0, remDnBase = 0, remArrUp = 0, remArrDn = 0;
    if (rank > 0)         { remUpBase = mapa_rank(smemBase, rank - 1); remArrUp = mapa_rank(mbarDn, rank - 1); }
    if (rank < NRANK - 1) { remDnBase = mapa_rank(smemBase, rank + 1); remArrDn = mapa_rank(mbarUp, rank + 1); }

    if (tid == 0) {
        mbar_init(mbarUp, 32);  // arrivals: rank-1's lrow15 warp
        mbar_init(mbarDn, 32);  // arrivals: rank+1's lrow0 warp
    }

    // signal -> smem
    sigs[tid] = sig[tid];

    // per-cell register state
    float sf[3][4];                     // stage field (input to current stage)
    float mx[4], my[4], mz[4];
    float ka[3][4];
    float Bx[4], By[4], Bz[4];
    float cex[4], cdem[4];
    unsigned meta = 0;                  // byte j: bits0-3 probe mask, bits4-5 srcid+1

    const int s0r = srcidx[0], s0c = srcidx[1];
    const int s1r = srcidx[2], s1c = srcidx[3];

#pragma unroll
    for (int j = 0; j < 4; j++) {
        int gc = grow * NXG + col + j;
        float ms = Msat[gc];
        cex[j]  = F_A2 / ms;
        cdem[j] = -F_MU0 * ms;
        Bx[j] = Bext[gc];
        By[j] = Bext[NXG * NXG + gc];
        Bz[j] = Bext[2 * NXG * NXG + gc];
        mx[j] = 0.0f; my[j] = 1.0f; mz[j] = 0.0f;
        sf[0][j] = 0.0f; sf[1][j] = 1.0f; sf[2][j] = 0.0f;
        ka[0][j] = ka[1][j] = ka[2][j] = 0.0f;
        unsigned mb = 0;
        if (grow == s0r && (col + j) == s0c) mb = 1u << 4;
        if (grow == s1r && (col + j) == s1c) mb = 2u << 4;
#pragma unroll
        for (int p = 0; p < NPROBE; p++) {
            if (grow == probeidx[2 * p] && (col + j) == probeidx[2 * p + 1]) {
                mb |= 1u << p;
                pms[p] = ms;
            }
        }
        meta |= mb << (8 * j);
    }

    // init bufA = m (incl. ghosts)
#pragma unroll
    for (int c = 0; c < 3; c++) {
        float4 f = make_float4(sf[c][0], sf[c][1], sf[c][2], sf[c][3]);
        *(float4*)(bufA + bidx(c, lrow, col)) = f;
        if (pushUp)      st_cluster4(remUpBase + 4u * (uint32_t)(BUFA_OFF + bidx(c, ROWS_PER, col)), f);
        else if (edgeUp) *(float4*)(bufA + bidx(c, -1, col)) = f;
        if (pushDn)      st_cluster4(remDnBase + 4u * (uint32_t)(BUFA_OFF + bidx(c, -1, col)), f);
        else if (edgeDn) *(float4*)(bufA + bidx(c, ROWS_PER, col)) = f;
    }
    cluster_sync_full();   // covers mbarrier init + initial ghost stores

    // -------------------------------------------------- relax (alpha = 0.5)
    for (int it = 0; it < RELAXN; ++it) {
        STAGE4(bufA, bufB, (uint32_t)BUFA_OFF, (uint32_t)BUFB_OFF, F_ALPHA_R, F_INV_R)
    }

    // capture m0 (z at probe cells) after relax
#pragma unroll
    for (int j = 0; j < 4; j++) {
        unsigned pm = (meta >> (8 * j)) & 0xFu;
        if (pm) {
#pragma unroll
            for (int p = 0; p < NPROBE; p++)
                if (pm & (1u << p)) pm0[p] = mz[j];
        }
    }

    // -------------------------------------------------- drive (alpha = 0.02)
    for (int t = 0; t < TSTEPS; ++t) {
        // inject source signal into Bz registers (set semantics)
#pragma unroll
        for (int j = 0; j < 4; j++) {
            unsigned sid = (meta >> (8 * j + 4)) & 3u;
            if (sid) Bz[j] = sigs[t * NSRC + (int)(sid - 1u)];
        }

        STAGE4(bufA, bufB, (uint32_t)BUFA_OFF, (uint32_t)BUFB_OFF, F_ALPHA_D, F_INV_D)

        // probe readout: (mz - m0z) * Msat
#pragma unroll
        for (int j = 0; j < 4; j++) {
            unsigned pm = (meta >> (8 * j)) & 0xFu;
            if (pm) {
#pragma unroll
                for (int p = 0; p < NPROBE; p++)
                    if (pm & (1u << p)) out[t * NPROBE + p] = (mz[j] - pm0[p]) * pms[p];
            }
        }
    }
}

extern "C" void kernel_launch(void* const* d_in, const int* in_sizes, int n_in,
                              void* d_out, int out_size) {
    (void)in_sizes; (void)n_in; (void)out_size;
    const float* sig    = (const float*)d_in[0];
    const float* Bext   = (const float*)d_in[1];
    const float* Msat   = (const float*)d_in[2];
    const int*   srci   = (const int*)d_in[3];
    const int*   probei = (const int*)d_in[4];
    float* out = (float*)d_out;

    const size_t smem_bytes = (size_t)SMEM_FLOATS * sizeof(float);
    cudaFuncSetAttribute(mm_solver_kernel,
                         cudaFuncAttributeMaxDynamicSharedMemorySize, (int)smem_bytes);
    mm_solver_kernel<<<NRANK, NTHREADS, smem_bytes>>>(sig, Bext, Msat, srci, probei, out);
}

// round 15
// speedup vs baseline: 1.7612x; 1.4727x over previous
#include <cuda_runtime.h>
#include <cstdint>

// ---------------------------------------------------------------- constants
#define NXG        128
#define TSTEPS     256
#define NSRC       2
#define NPROBE     4
#define RELAXN     100

#define F_H      ((float)(175950000000.0 * 1e-13))        // GAMMA*DT
#define F_H2     (0.5f * F_H)
#define F_H6     ((float)(175950000000.0 * 1e-13 / 6.0))
#define F_MU0    ((float)(4e-07 * 3.14159265358979323846)) // MU0
#define F_A2     ((float)(2.0 * 1.3e-11))                  // 2*A_EX
#define F_CSOT   (0.001f)
#define F_INVDX2 (1.0f / ((float)(5e-09 * 5e-09)))
#define F_ALPHA_R 0.5f
#define F_INV_R   ((float)(1.0 / (1.0 + 0.5 * 0.5)))
#define F_ALPHA_D 0.02f
#define F_INV_D   ((float)(1.0 / (1.0 + 0.02 * 0.02)))

// buffer: [comp][row -1..RP][col]
template <int RP>
__device__ __forceinline__ int bidx(int c, int r, int col) {
    return (c * (RP + 2) + (r + 1)) * NXG + col;
}

// smem layout (in floats), parameterized by rows-per-CTA
template <int RP> struct SMap {
    static constexpr int BUF   = 3 * (RP + 2) * NXG;
    static constexpr int BUFA  = 0;
    static constexpr int BUFB  = BUF;
    static constexpr int SIGS  = 2 * BUF;
    static constexpr int MBARU = SIGS + TSTEPS * NSRC;   // even index -> 8B aligned
    static constexpr int MBARD = MBARU + 2;
    static constexpr int PMS   = MBARD + 2;
    static constexpr int PM0   = PMS + 4;
    static constexpr int TOTAL = PM0 + 4;
};

// ---------------------------------------------------------------- ptx helpers
__device__ __forceinline__ void cluster_sync_full() {
    asm volatile("barrier.cluster.arrive.aligned;" ::: "memory");
    asm volatile("barrier.cluster.wait.aligned;" ::: "memory");
}
__device__ __forceinline__ uint32_t smem_u32(const void* p) {
    return (uint32_t)__cvta_generic_to_shared(p);
}
__device__ __forceinline__ uint32_t mapa_rank(uint32_t laddr, unsigned r) {
    uint32_t ra;
    asm("mapa.shared::cluster.u32 %0, %1, %2;" : "=r"(ra) : "r"(laddr), "r"(r));
    return ra;
}
__device__ __forceinline__ void st_cluster4(uint32_t addr, float4 v) {
    asm volatile("st.shared::cluster.v4.f32 [%0], {%1,%2,%3,%4};"
                 :: "r"(addr), "f"(v.x), "f"(v.y), "f"(v.z), "f"(v.w) : "memory");
}
__device__ __forceinline__ void mbar_init(uint32_t addr, unsigned cnt) {
    asm volatile("mbarrier.init.shared.b64 [%0], %1;" :: "r"(addr), "r"(cnt) : "memory");
}
__device__ __forceinline__ void mbar_arrive_remote(uint32_t raddr) {
    asm volatile("mbarrier.arrive.release.cluster.shared::cluster.b64 _, [%0];"
                 :: "r"(raddr) : "memory");
}
__device__ __forceinline__ void mbar_wait(uint32_t addr, uint32_t parity) {
    asm volatile(
        "{\n\t"
        ".reg .pred P;\n\t"
        "WL_%=:\n\t"
        "mbarrier.try_wait.parity.acquire.cluster.shared::cta.b64 P, [%0], %1, 0x989680;\n\t"
        "@P bra WD_%=;\n\t"
        "bra WL_%=;\n\t"
        "WD_%=:\n\t"
        "}" :: "r"(addr), "r"(parity) : "memory");
}

// ---------------------------------------------------------------- one RK4 stage
template <int S, int RP>
__device__ __forceinline__ void stage(const float* __restrict__ src, float* __restrict__ dst,
                                      uint32_t dstFloatOff,
                                      int lrow, int col, int lane,
                                      bool pushUp, bool pushDn, bool edgeUp, bool edgeDn,
                                      uint32_t remUpBase, uint32_t remDnBase,
                                      float (&sf)[3][4],
                                      float (&mx)[4], float (&my)[4], float (&mz)[4],
                                      float (&ka)[3][4],
                                      const float (&Bx)[4], const float (&By)[4], const float (&Bz)[4],
                                      const float (&cex)[4], const float (&cdem)[4],
                                      float alpha, float inv) {
    // vertical neighbors from SMEM (6 x LDS.128)
    float u[3][4], d[3][4];
#pragma unroll
    for (int c = 0; c < 3; c++) {
        float4 uv = *(const float4*)(src + bidx<RP>(c, lrow - 1, col));
        float4 dv = *(const float4*)(src + bidx<RP>(c, lrow + 1, col));
        u[c][0] = uv.x; u[c][1] = uv.y; u[c][2] = uv.z; u[c][3] = uv.w;
        d[c][0] = dv.x; d[c][1] = dv.y; d[c][2] = dv.z; d[c][3] = dv.w;
    }
    // horizontal neighbors via shuffle (edge-replicate at lanes 0/31)
    float lfv[3], rtv[3];
#pragma unroll
    for (int c = 0; c < 3; c++) {
        float l = __shfl_up_sync(0xffffffffu, sf[c][3], 1);
        float r = __shfl_down_sync(0xffffffffu, sf[c][0], 1);
        lfv[c] = (lane == 0)  ? sf[c][0] : l;
        rtv[c] = (lane == 31) ? sf[c][3] : r;
    }

    float nin[3][4];
#pragma unroll
    for (int j = 0; j < 4; j++) {
        float lap[3];
#pragma unroll
        for (int c = 0; c < 3; c++) {
            float lv = (j == 0) ? lfv[c] : sf[c][j - 1];
            float rv = (j == 3) ? rtv[c] : sf[c][j + 1];
            // match JAX order: down + up + right + left - 4*m
            lap[c] = (d[c][j] + u[c][j] + rv + lv - 4.0f * sf[c][j]) * F_INVDX2;
        }
        float ax = sf[0][j], ay = sf[1][j], az = sf[2][j];
        float bx = Bx[j] + cex[j] * lap[0];
        float by = By[j] + cex[j] * lap[1];
        float bz = Bz[j] + cex[j] * lap[2] + cdem[j] * az;
        // c1 = m x b
        float c1x = ay * bz - az * by;
        float c1y = az * bx - ax * bz;
        float c1z = ax * by - ay * bx;
        // c2 = m x c1
        float c2x = ay * c1z - az * c1y;
        float c2y = az * c1x - ax * c1z;
        float c2z = ax * c1y - ay * c1x;
        // sot = C_SOT * m x (m x yhat)
        float sx = F_CSOT * (ay * ax);
        float sy = F_CSOT * (az * (-az) - ax * ax);
        float sz = F_CSOT * (ay * az);
        float kx = -inv * (c1x + alpha * c2x) + sx;
        float ky = -inv * (c1y + alpha * c2y) + sy;
        float kz = -inv * (c1z + alpha * c2z) + sz;

        if (S == 0)      { ka[0][j] = kx;         ka[1][j] = ky;         ka[2][j] = kz; }
        else if (S < 3)  { ka[0][j] += 2.0f * kx; ka[1][j] += 2.0f * ky; ka[2][j] += 2.0f * kz; }

        if (S < 3) {
            const float cc = (S == 2) ? F_H : F_H2;
            nin[0][j] = mx[j] + cc * kx;
            nin[1][j] = my[j] + cc * ky;
            nin[2][j] = mz[j] + cc * kz;
        } else {
            mx[j] = mx[j] + F_H6 * (ka[0][j] + kx);
            my[j] = my[j] + F_H6 * (ka[1][j] + ky);
            mz[j] = mz[j] + F_H6 * (ka[2][j] + kz);
            nin[0][j] = mx[j]; nin[1][j] = my[j]; nin[2][j] = mz[j];
        }
    }

    // store interior row + ghost push / edge replicate; update register stage field
#pragma unroll
    for (int c = 0; c < 3; c++) {
        float4 f = make_float4(nin[c][0], nin[c][1], nin[c][2], nin[c][3]);
        *(float4*)(dst + bidx<RP>(c, lrow, col)) = f;
        if (pushUp)      st_cluster4(remUpBase + 4u * (dstFloatOff + (uint32_t)bidx<RP>(c, RP, col)), f);
        else if (edgeUp) *(float4*)(dst + bidx<RP>(c, -1, col)) = f;
        if (pushDn)      st_cluster4(remDnBase + 4u * (dstFloatOff + (uint32_t)bidx<RP>(c, -1, col)), f);
        else if (edgeDn) *(float4*)(dst + bidx<RP>(c, RP, col)) = f;
        sf[c][0] = nin[c][0]; sf[c][1] = nin[c][1]; sf[c][2] = nin[c][2]; sf[c][3] = nin[c][3];
    }
}

// per-stage sync tail
__device__ __forceinline__ void sync_tail(uint32_t parity,
                                          bool pushUp, bool pushDn,
                                          uint32_t mbarUp, uint32_t mbarDn,
                                          uint32_t remArrUp, uint32_t remArrDn) {
    if (pushUp) mbar_arrive_remote(remArrUp);  // signal rank-1's mbar_dn
    if (pushDn) mbar_arrive_remote(remArrDn);  // signal rank+1's mbar_up
    __syncthreads();
    if (pushUp) mbar_wait(mbarUp, parity);     // wait for rank-1's ghosts
    if (pushDn) mbar_wait(mbarDn, parity);     // wait for rank+1's ghosts
}

#define STAGE4(SRC, DST, DSTOFF_A, DSTOFF_B, ALPHA, INV)                                           \
    stage<0, RP>(SRC, DST, DSTOFF_B, lrow, col, lane, pushUp, pushDn, edgeUp, edgeDn,              \
             remUpBase, remDnBase, sf, mx, my, mz, ka, Bx, By, Bz, cex, cdem, ALPHA, INV);         \
    sync_tail(0u, pushUp, pushDn, mbarUp, mbarDn, remArrUp, remArrDn);                             \
    stage<1, RP>(DST, SRC, DSTOFF_A, lrow, col, lane, pushUp, pushDn, edgeUp, edgeDn,              \
             remUpBase, remDnBase, sf, mx, my, mz, ka, Bx, By, Bz, cex, cdem, ALPHA, INV);         \
    sync_tail(1u, pushUp, pushDn, mbarUp, mbarDn, remArrUp, remArrDn);                             \
    stage<2, RP>(SRC, DST, DSTOFF_B, lrow, col, lane, pushUp, pushDn, edgeUp, edgeDn,              \
             remUpBase, remDnBase, sf, mx, my, mz, ka, Bx, By, Bz, cex, cdem, ALPHA, INV);         \
    sync_tail(0u, pushUp, pushDn, mbarUp, mbarDn, remArrUp, remArrDn);                             \
    stage<3, RP>(DST, SRC, DSTOFF_A, lrow, col, lane, pushUp, pushDn, edgeUp, edgeDn,              \
             remUpBase, remDnBase, sf, mx, my, mz, ka, Bx, By, Bz, cex, cdem, ALPHA, INV);         \
    sync_tail(1u, pushUp, pushDn, mbarUp, mbarDn, remArrUp, remArrDn);

template <int NRANK_T>
__global__ void __launch_bounds__(32 * (128 / NRANK_T), 1)
mm_solver_kernel(const float* __restrict__ sig, const float* __restrict__ Bext,
                 const float* __restrict__ Msat, const int* __restrict__ srcidx,
                 const int* __restrict__ probeidx, float* __restrict__ out) {
    constexpr int RP = 128 / NRANK_T;     // rows per CTA
    constexpr int NT = RP * 32;           // threads per CTA
    using M = SMap<RP>;

    extern __shared__ float smem[];
    float* bufA = smem + M::BUFA;
    float* bufB = smem + M::BUFB;
    float* sigs = smem + M::SIGS;
    float* pms  = smem + M::PMS;
    float* pm0  = smem + M::PM0;

    const unsigned rank = blockIdx.x;
    const int tid  = threadIdx.x;
    const int lrow = tid >> 5;            // 0..RP-1 (warp-uniform)
    const int lane = tid & 31;
    const int col  = lane * 4;            // 0,4,...,124
    const int grow = (int)rank * RP + lrow;

    const bool pushUp = (lrow == 0)      && (rank > 0);
    const bool edgeUp = (lrow == 0)      && (rank == 0);
    const bool pushDn = (lrow == RP - 1) && (rank < NRANK_T - 1);
    const bool edgeDn = (lrow == RP - 1) && (rank == NRANK_T - 1);

    const uint32_t smemBase = smem_u32(smem);
    const uint32_t mbarUp   = smemBase + 4u * M::MBARU;
    const uint32_t mbarDn   = smemBase + 4u * M::MBARD;
    uint32_t remUpBase = 0, remDnBase = 0, remArrUp = 0, remArrDn = 0;
    if (rank > 0)           { remUpBase = mapa_rank(smemBase, rank - 1); remArrUp = mapa_rank(mbarDn, rank - 1); }
    if (rank < NRANK_T - 1) { remDnBase = mapa_rank(smemBase, rank + 1); remArrDn = mapa_rank(mbarUp, rank + 1); }

    if (tid == 0) {
        mbar_init(mbarUp, 32);  // arrivals: rank-1's last-row warp
        mbar_init(mbarDn, 32);  // arrivals: rank+1's first-row warp
    }

    // signal -> smem (TSTEPS*NSRC floats)
    for (int i = tid; i < TSTEPS * NSRC; i += NT) sigs[i] = sig[i];

    // per-cell register state
    float sf[3][4];                     // stage field (input to current stage)
    float mx[4], my[4], mz[4];
    float ka[3][4];
    float Bx[4], By[4], Bz[4];
    float cex[4], cdem[4];
    unsigned meta = 0;                  // byte j: bits0-3 probe mask, bits4-5 srcid+1

    const int s0r = srcidx[0], s0c = srcidx[1];
    const int s1r = srcidx[2], s1c = srcidx[3];

#pragma unroll
    for (int j = 0; j < 4; j++) {
        int gc = grow * NXG + col + j;
        float ms = Msat[gc];
        cex[j]  = F_A2 / ms;
        cdem[j] = -F_MU0 * ms;
        Bx[j] = Bext[gc];
        By[j] = Bext[NXG * NXG + gc];
        Bz[j] = Bext[2 * NXG * NXG + gc];
        mx[j] = 0.0f; my[j] = 1.0f; mz[j] = 0.0f;
        sf[0][j] = 0.0f; sf[1][j] = 1.0f; sf[2][j] = 0.0f;
        ka[0][j] = ka[1][j] = ka[2][j] = 0.0f;
        unsigned mb = 0;
        if (grow == s0r && (col + j) == s0c) mb = 1u << 4;
        if (grow == s1r && (col + j) == s1c) mb = 2u << 4;
#pragma unroll
        for (int p = 0; p < NPROBE; p++) {
            if (grow == probeidx[2 * p] && (col + j) == probeidx[2 * p + 1]) {
                mb |= 1u << p;
                pms[p] = ms;
            }
        }
        meta |= mb << (8 * j);
    }

    // init bufA = m (incl. ghosts)
#pragma unroll
    for (int c = 0; c < 3; c++) {
        float4 f = make_float4(sf[c][0], sf[c][1], sf[c][2], sf[c][3]);
        *(float4*)(bufA + bidx<RP>(c, lrow, col)) = f;
        if (pushUp)      st_cluster4(remUpBase + 4u * (uint32_t)(M::BUFA + bidx<RP>(c, RP, col)), f);
        else if (edgeUp) *(float4*)(bufA + bidx<RP>(c, -1, col)) = f;
        if (pushDn)      st_cluster4(remDnBase + 4u * (uint32_t)(M::BUFA + bidx<RP>(c, -1, col)), f);
        else if (edgeDn) *(float4*)(bufA + bidx<RP>(c, RP, col)) = f;
    }
    cluster_sync_full();   // covers mbarrier init + initial ghost stores

    // -------------------------------------------------- relax (alpha = 0.5)
    for (int it = 0; it < RELAXN; ++it) {
        STAGE4(bufA, bufB, (uint32_t)M::BUFA, (uint32_t)M::BUFB, F_ALPHA_R, F_INV_R)
    }

    // capture m0 (z at probe cells) after relax
#pragma unroll
    for (int j = 0; j < 4; j++) {
        unsigned pm = (meta >> (8 * j)) & 0xFu;
        if (pm) {
#pragma unroll
            for (int p = 0; p < NPROBE; p++)
                if (pm & (1u << p)) pm0[p] = mz[j];
        }
    }

    // -------------------------------------------------- drive (alpha = 0.02)
    for (int t = 0; t < TSTEPS; ++t) {
        // inject source signal into Bz registers (set semantics)
#pragma unroll
        for (int j = 0; j < 4; j++) {
            unsigned sid = (meta >> (8 * j + 4)) & 3u;
            if (sid) Bz[j] = sigs[t * NSRC + (int)(sid - 1u)];
        }

        STAGE4(bufA, bufB, (uint32_t)M::BUFA, (uint32_t)M::BUFB, F_ALPHA_D, F_INV_D)

        // probe readout: (mz - m0z) * Msat
#pragma unroll
        for (int j = 0; j < 4; j++) {
            unsigned pm = (meta >> (8 * j)) & 0xFu;
            if (pm) {
#pragma unroll
                for (int p = 0; p < NPROBE; p++)
                    if (pm & (1u << p)) out[t * NPROBE + p] = (mz[j] - pm0[p]) * pms[p];
            }
        }
    }
}

extern "C" void kernel_launch(void* const* d_in, const int* in_sizes, int n_in,
                              void* d_out, int out_size) {
    (void)in_sizes; (void)n_in; (void)out_size;
    const float* sig    = (const float*)d_in[0];
    const float* Bext   = (const float*)d_in[1];
    const float* Msat   = (const float*)d_in[2];
    const int*   srci   = (const int*)d_in[3];
    const int*   probei = (const int*)d_in[4];
    float* out = (float*)d_out;

    const size_t smem16 = (size_t)SMap<8>::TOTAL  * sizeof(float);  // NRANK=16 -> RP=8
    const size_t smem8  = (size_t)SMap<16>::TOTAL * sizeof(float);  // NRANK=8  -> RP=16

    cudaFuncSetAttribute(mm_solver_kernel<16>,
                         cudaFuncAttributeMaxDynamicSharedMemorySize, (int)smem16);
    cudaFuncSetAttribute(mm_solver_kernel<16>,
                         cudaFuncAttributeNonPortableClusterSizeAllowed, 1);
    cudaFuncSetAttribute(mm_solver_kernel<8>,
                         cudaFuncAttributeMaxDynamicSharedMemorySize, (int)smem8);

    // Query max admissible cluster size for the 16-CTA variant (host-side, capture-safe).
    int cs = 0;
    {
        cudaLaunchConfig_t q = {};
        q.gridDim = {16, 1, 1};
        q.blockDim = {256, 1, 1};
        q.dynamicSmemBytes = smem16;
        q.attrs = nullptr; q.numAttrs = 0;
        if (cudaOccupancyMaxPotentialClusterSize(&cs, mm_solver_kernel<16>, &q) != cudaSuccess)
            cs = 0;
    }

    cudaLaunchConfig_t cfg = {};
    cudaLaunchAttribute attr[1];
    attr[0].id = cudaLaunchAttributeClusterDimension;
    cfg.attrs = attr;
    cfg.numAttrs = 1;

    if (cs >= 16) {
        cfg.gridDim = {16, 1, 1};
        cfg.blockDim = {256, 1, 1};
        cfg.dynamicSmemBytes = smem16;
        attr[0].val.clusterDim = {16, 1, 1};
        cudaLaunchKernelEx(&cfg, mm_solver_kernel<16>, sig, Bext, Msat, srci, probei, out);
    } else {
        cfg.gridDim = {8, 1, 1};
        cfg.blockDim = {512, 1, 1};
        cfg.dynamicSmemBytes = smem8;
        attr[0].val.clusterDim = {8, 1, 1};
        cudaLaunchKernelEx(&cfg, mm_solver_kernel<8>, sig, Bext, Msat, srci, probei, out);
    }
}